// round 17
// baseline (speedup 1.0000x reference)
#include <cuda_runtime.h>
#include <cuda_fp16.h>
#include <math.h>
#include <stdint.h>

// ---------------------------------------------------------------------------
// Problem constants
// ---------------------------------------------------------------------------
constexpr int H    = 2048;
constexpr int NH   = 16;
constexpr int NOPE = 128;
constexpr int ROPE = 64;
constexpr int VD   = 128;
constexpr int QR   = 1024;
constexpr int KVR  = 512;
constexpr int BB   = 2;       // batch
constexpr int S    = 2048;    // seq len
constexpr int T    = BB * S;  // 4096 tokens
constexpr float EPS = 1e-6f;
constexpr float SM_SCALE2 = 0.10412105626079532f;         // (1/sqrt(192)) * log2(e)
constexpr float MASK2 = -1.4426950408889634e9f;           // -1e9 * log2(e)

// ---------------------------------------------------------------------------
// Device scratch (allocation-free rule: __device__ globals)
// ---------------------------------------------------------------------------
__device__ float g_cq   [T * QR];
__device__ float g_ckv  [T * KVR];
__device__ float g_qrope_f[T * NH * ROPE];   // GEMM fp32 out (pre-rope)
__device__ float g_krope_f[T * ROPE];
__device__ float g_attn [T * NH * VD];
__device__ float g_ctab [S * (ROPE / 2)];
__device__ float g_stab [S * (ROPE / 2)];
__device__ __align__(16) __half g_qnope_h[T * NH * NOPE];
__device__ __align__(16) __half g_knope_h[T * NH * NOPE];
__device__ __align__(16) __half g_qrope_h[T * NH * ROPE];
__device__ __align__(16) __half g_krope_h[T * ROPE];
__device__ __align__(16) __half g_v_h    [T * NH * VD];

// ---------------------------------------------------------------------------
// fp16 helpers
// ---------------------------------------------------------------------------
__device__ __forceinline__ uint32_t h2_as_u32(__half2 h) {
    return *reinterpret_cast<uint32_t*>(&h);
}

__device__ __forceinline__ void mma_f16(float& c0, float& c1, float& c2, float& c3,
                                        uint32_t a0, uint32_t a1, uint32_t a2, uint32_t a3,
                                        uint32_t b0, uint32_t b1)
{
    asm volatile(
        "mma.sync.aligned.m16n8k16.row.col.f32.f16.f16.f32 "
        "{%0,%1,%2,%3}, {%4,%5,%6,%7}, {%8,%9}, {%0,%1,%2,%3};\n"
        : "+f"(c0), "+f"(c1), "+f"(c2), "+f"(c3)
        : "r"(a0), "r"(a1), "r"(a2), "r"(a3), "r"(b0), "r"(b1));
}

__device__ __forceinline__ uint32_t prmt(uint32_t a, uint32_t b, uint32_t sel) {
    uint32_t r;
    asm("prmt.b32 %0, %1, %2, %3;" : "=r"(r) : "r"(a), "r"(b), "r"(sel));
    return r;
}

// fp16 A-fragment smem store (m16n8k16), KSTEPS = k16-steps per tile.
// v holds 8 consecutive k halves (4 half2) for row m starting at k.
template<int KSTEPS>
__device__ __forceinline__ void st_afrag_h(uint32_t* F, int m, int k, uint4 v) {
    int slot = ((m >> 3) & 1) + (((k >> 3) & 1) << 1);
    uint32_t* dst = F + ((((m >> 4) * KSTEPS + (k >> 4)) * 4 + slot) << 5) + (m & 7) * 4;
    *(uint4*)dst = v;
}
// fp16 B-fragment smem store for attention K tiles (row n, k-groups).
template<int KSTEPS>
__device__ __forceinline__ void st_bfrag_h(uint32_t* F, int n, int k, uint4 v) {
    int slot = (k >> 3) & 1;
    uint32_t* dst = F + ((((n >> 3) * KSTEPS + (k >> 4)) * 2 + slot) << 5) + (n & 7) * 4;
    *(uint4*)dst = v;
}

// ---------------------------------------------------------------------------
// fp16 tensor-core GEMM: C[M,N] = A[M,K] @ B[K,N], fp32 in (cvt at staging),
// fp32 or fp16 out. 128x128 tile, BK=16, 256 threads, warp tile 64x32.
// A staged in A-frag order; B staged k-pair packed (half2=(k,k+1)).
// ---------------------------------------------------------------------------
constexpr int GB_STR = 136;   // uint32 stride: reads rid*8+qid conflict-free

__global__ void __launch_bounds__(256)
f16_gemm_kernel(const float* __restrict__ A, const float* __restrict__ B,
                float* __restrict__ C, __half* __restrict__ Ch,
                int M, int N, int K, int round_out)
{
    __shared__ uint32_t Ash[2][8 * 4 * 32];    // A-frag: 8 mtiles x 1 kstep
    __shared__ uint32_t Bsh[2][8 * GB_STR];    // B k-pairs: 8 rowpairs x 128n

    const int tid  = threadIdx.x;
    const int lane = tid & 31;
    const int warp = tid >> 5;
    const int qid  = lane >> 2;
    const int rid  = lane & 3;
    const int wrm  = (warp >> 2) * 4;    // mtile base (rows (warp>>2)*64)
    const int wc   = (warp & 3) * 32;    // col base

    const int rowBase = blockIdx.y * 128;
    const int colBase = blockIdx.x * 128;

    // staging indices
    const int ar = tid & 127;            // A row
    const int ag = (tid >> 7) * 8;       // A k-group base (0 or 8)
    const int brp = tid >> 5;            // B row pair 0..7
    const int bn  = (tid & 31) * 4;      // B col base
    const int gn  = colBase + bn;
    const bool bok = (gn < N);

    float acc[4][4][4];
#pragma unroll
    for (int i = 0; i < 4; i++)
#pragma unroll
        for (int j = 0; j < 4; j++)
#pragma unroll
            for (int c = 0; c < 4; c++) acc[i][j][c] = 0.f;

    const int nt = K / 16;
    float4 af0, af1, bf0, bf1;

    // prologue: tile 0
    af0 = *(const float4*)&A[(size_t)(rowBase + ar) * K + ag];
    af1 = *(const float4*)&A[(size_t)(rowBase + ar) * K + ag + 4];
    bf0 = bok ? *(const float4*)&B[(size_t)(2 * brp)     * N + gn] : make_float4(0,0,0,0);
    bf1 = bok ? *(const float4*)&B[(size_t)(2 * brp + 1) * N + gn] : make_float4(0,0,0,0);
    {
        uint4 ua, ub;
        ua.x = h2_as_u32(__floats2half2_rn(af0.x, af0.y));
        ua.y = h2_as_u32(__floats2half2_rn(af0.z, af0.w));
        ua.z = h2_as_u32(__floats2half2_rn(af1.x, af1.y));
        ua.w = h2_as_u32(__floats2half2_rn(af1.z, af1.w));
        st_afrag_h<1>(Ash[0], ar, ag, ua);
        ub.x = h2_as_u32(__floats2half2_rn(bf0.x, bf1.x));
        ub.y = h2_as_u32(__floats2half2_rn(bf0.y, bf1.y));
        ub.z = h2_as_u32(__floats2half2_rn(bf0.z, bf1.z));
        ub.w = h2_as_u32(__floats2half2_rn(bf0.w, bf1.w));
        *(uint4*)&Bsh[0][brp * GB_STR + bn] = ub;
    }
    __syncthreads();

    for (int t = 0; t < nt; t++) {
        const int buf = t & 1;

        if (t + 1 < nt) {
            const int k0 = (t + 1) * 16;
            af0 = *(const float4*)&A[(size_t)(rowBase + ar) * K + k0 + ag];
            af1 = *(const float4*)&A[(size_t)(rowBase + ar) * K + k0 + ag + 4];
            bf0 = bok ? *(const float4*)&B[(size_t)(k0 + 2 * brp)     * N + gn] : make_float4(0,0,0,0);
            bf1 = bok ? *(const float4*)&B[(size_t)(k0 + 2 * brp + 1) * N + gn] : make_float4(0,0,0,0);
        }

        // compute on current buffer: 4x4 m16n8k16 mma per warp
        {
            uint32_t b[4][2];
#pragma unroll
            for (int j = 0; j < 4; j++) {
                b[j][0] = Bsh[buf][rid * GB_STR       + wc + j * 8 + qid];
                b[j][1] = Bsh[buf][(rid + 4) * GB_STR + wc + j * 8 + qid];
            }
#pragma unroll
            for (int i = 0; i < 4; i++) {
                const uint32_t* ap = &Ash[buf][(((wrm + i) * 4) << 5) + lane];
                uint32_t a0 = ap[0], a1 = ap[32], a2 = ap[64], a3 = ap[96];
#pragma unroll
                for (int j = 0; j < 4; j++)
                    mma_f16(acc[i][j][0], acc[i][j][1], acc[i][j][2], acc[i][j][3],
                            a0, a1, a2, a3, b[j][0], b[j][1]);
            }
        }

        if (t + 1 < nt) {
            const int nb = (t + 1) & 1;
            uint4 ua, ub;
            ua.x = h2_as_u32(__floats2half2_rn(af0.x, af0.y));
            ua.y = h2_as_u32(__floats2half2_rn(af0.z, af0.w));
            ua.z = h2_as_u32(__floats2half2_rn(af1.x, af1.y));
            ua.w = h2_as_u32(__floats2half2_rn(af1.z, af1.w));
            st_afrag_h<1>(Ash[nb], ar, ag, ua);
            ub.x = h2_as_u32(__floats2half2_rn(bf0.x, bf1.x));
            ub.y = h2_as_u32(__floats2half2_rn(bf0.y, bf1.y));
            ub.z = h2_as_u32(__floats2half2_rn(bf0.z, bf1.z));
            ub.w = h2_as_u32(__floats2half2_rn(bf0.w, bf1.w));
            *(uint4*)&Bsh[nb][brp * GB_STR + bn] = ub;
        }
        __syncthreads();
    }

    // epilogue (same C layout as before)
#pragma unroll
    for (int i = 0; i < 4; i++) {
        const int r0 = rowBase + (wrm + i) * 16 + qid;
#pragma unroll
        for (int j = 0; j < 4; j++) {
            const int col = colBase + wc + j * 8 + rid * 2;
            if (col < N) {
                if (Ch) {
                    *(__half2*)&Ch[(size_t)r0 * N + col] =
                        __floats2half2_rn(acc[i][j][0], acc[i][j][1]);
                    *(__half2*)&Ch[(size_t)(r0 + 8) * N + col] =
                        __floats2half2_rn(acc[i][j][2], acc[i][j][3]);
                } else {
                    *(float2*)&C[(size_t)r0 * N + col] =
                        make_float2(acc[i][j][0], acc[i][j][1]);
                    *(float2*)&C[(size_t)(r0 + 8) * N + col] =
                        make_float2(acc[i][j][2], acc[i][j][3]);
                }
            }
        }
    }
    (void)round_out;
}

// ---------------------------------------------------------------------------
// RMSNorm (in place)
// ---------------------------------------------------------------------------
__global__ void rmsnorm_kernel(float* __restrict__ x,
                               const float* __restrict__ scale, int D)
{
    __shared__ float red[32];
    float* p = x + (size_t)blockIdx.x * D;

    float ss = 0.f;
    for (int d = threadIdx.x; d < D; d += blockDim.x) {
        float v = p[d];
        ss += v * v;
    }
#pragma unroll
    for (int o = 16; o; o >>= 1) ss += __shfl_xor_sync(0xffffffffu, ss, o);
    if ((threadIdx.x & 31) == 0) red[threadIdx.x >> 5] = ss;
    __syncthreads();
    if (threadIdx.x < 32) {
        float v = (threadIdx.x < (blockDim.x >> 5)) ? red[threadIdx.x] : 0.f;
#pragma unroll
        for (int o = 16; o; o >>= 1) v += __shfl_xor_sync(0xffffffffu, v, o);
        if (threadIdx.x == 0) red[0] = v;
    }
    __syncthreads();
    float inv = rsqrtf(red[0] / (float)D + EPS);
    for (int d = threadIdx.x; d < D; d += blockDim.x)
        p[d] = p[d] * inv * scale[d];
}

// ---------------------------------------------------------------------------
// RoPE tables / application (rope kernels emit fp16 for the attention mma)
// ---------------------------------------------------------------------------
__global__ void rope_table_kernel(float* __restrict__ ctab, float* __restrict__ stab)
{
    int idx = blockIdx.x * blockDim.x + threadIdx.x;
    if (idx >= S * (ROPE / 2)) return;
    int i = idx % (ROPE / 2);
    int s = idx / (ROPE / 2);
    float freq = (float)pow(10000.0, -((double)(2 * i)) / (double)ROPE);
    float ang  = (float)s * freq;
    double a   = (double)ang;
    ctab[idx] = (float)cos(a);
    stab[idx] = (float)sin(a);
}

__global__ void rope_q_kernel(const float* __restrict__ qf, __half* __restrict__ qh,
                              const float* __restrict__ ctab,
                              const float* __restrict__ stab)
{
    int idx = blockIdx.x * blockDim.x + threadIdx.x;
    if (idx >= T * NH * (ROPE / 2)) return;
    int i   = idx & 31;
    int rem = idx >> 5;
    int h   = rem & (NH - 1);
    int tok = rem >> 4;
    int s   = tok & (S - 1);
    float c  = ctab[s * 32 + i];
    float sn = stab[s * 32 + i];
    size_t off = (size_t)tok * (NH * ROPE) + h * ROPE + 2 * i;
    float x1 = qf[off], x2 = qf[off + 1];
    *(__half2*)&qh[off] = __floats2half2_rn(x1 * c - x2 * sn, x1 * sn + x2 * c);
}

__global__ void rope_k_kernel(const float* __restrict__ kf, __half* __restrict__ kh,
                              const float* __restrict__ ctab,
                              const float* __restrict__ stab)
{
    int idx = blockIdx.x * blockDim.x + threadIdx.x;
    if (idx >= T * (ROPE / 2)) return;
    int i   = idx & 31;
    int tok = idx >> 5;
    int s   = tok & (S - 1);
    float c  = ctab[s * 32 + i];
    float sn = stab[s * 32 + i];
    size_t off = (size_t)tok * ROPE + 2 * i;
    float x1 = kf[off], x2 = kf[off + 1];
    *(__half2*)&kh[off] = __floats2half2_rn((x1 * c - x2 * sn) * 0.0625f,
                                            (x1 * sn + x2 * c) * 0.0625f);
}

// ---------------------------------------------------------------------------
// Flash attention: BQ=128, 512 threads. QK AND PV on fp16 m16n8k16.
// (round-16 kernel, unchanged)
// ---------------------------------------------------------------------------
constexpr int BQ  = 128;
constexpr int BKT = 64;
constexpr int VSTRH = 136;
constexpr int PSTRH = 36;

struct AttnSmem {
    uint32_t Qf[8 * 12 * 4 * 32];
    uint32_t Kf[8 * 12 * 2 * 32];
    uint32_t Vh[32 * VSTRH];
    uint32_t Ph[BQ * PSTRH];
    float rowmax[2][BQ];
    float rowsum[2][BQ];
};

__global__ void __launch_bounds__(512)
attn_kernel(const __half* __restrict__ qn, const __half* __restrict__ qr,
            const __half* __restrict__ kn, const __half* __restrict__ kr,
            const __half* __restrict__ v,  float* __restrict__ out)
{
    extern __shared__ char smraw[];
    AttnSmem& sm = *reinterpret_cast<AttnSmem*>(smraw);

    const int qt = (gridDim.x - 1) - blockIdx.x;
    const int h  = blockIdx.y;
    const int b  = blockIdx.z;
    const int tid = threadIdx.x;
    const int lane = tid & 31;
    const int warp = tid >> 5;
    const int qid  = lane >> 2;
    const int rid  = lane & 3;
    const int qb = b * S + qt * BQ;

    const int mtile = warp & 7;
    const int half  = warp >> 3;
    const int ntb   = half * 4;
    const int row0 = mtile * 16 + qid;
    const int nbv  = half * 64;

    const int krow = tid & 63;
    const int kg   = tid >> 6;
    const int vrp  = tid >> 4;
    const int vcg  = (tid & 15) * 8;

    for (int idx = tid; idx < BQ * 16; idx += 512) {
        int r = idx & 127, g = idx >> 7;
        uint4 u = *(const uint4*)&qn[(size_t)(qb + r) * (NH * NOPE) + h * NOPE + g * 8];
        st_afrag_h<12>(sm.Qf, r, g * 8, u);
    }
    for (int idx = tid; idx < BQ * 8; idx += 512) {
        int r = idx & 127, g = idx >> 7;
        uint4 u = *(const uint4*)&qr[(size_t)(qb + r) * (NH * ROPE) + h * ROPE + g * 8];
        st_afrag_h<12>(sm.Qf, r, 128 + g * 8, u);
    }

    float m0 = -1e30f, m1 = -1e30f, l0 = 0.f, l1 = 0.f;
    float acc[8][4];
#pragma unroll
    for (int j = 0; j < 8; j++)
#pragma unroll
        for (int c = 0; c < 4; c++) acc[j][c] = 0.f;

    const int nkt = 2 * qt + 2;

    uint4 kb[3], vlo, vhi;
    {
        const int kbT = b * S;
        kb[0] = *(const uint4*)&kn[(size_t)(kbT + krow) * (NH * NOPE) + h * NOPE + kg * 8];
        kb[1] = *(const uint4*)&kn[(size_t)(kbT + krow) * (NH * NOPE) + h * NOPE + kg * 8 + 64];
        kb[2] = *(const uint4*)&kr[(size_t)(kbT + krow) * ROPE + kg * 8];
        vlo = *(const uint4*)&v[(size_t)(kbT + 2 * vrp)     * (NH * VD) + h * VD + vcg];
        vhi = *(const uint4*)&v[(size_t)(kbT + 2 * vrp + 1) * (NH * VD) + h * VD + vcg];
    }
    st_bfrag_h<12>(sm.Kf, krow, kg * 8, kb[0]);
    st_bfrag_h<12>(sm.Kf, krow, kg * 8 + 64, kb[1]);
    st_bfrag_h<12>(sm.Kf, krow, 128 + kg * 8, kb[2]);
    __syncthreads();
    if (1 < nkt) {
        const int kbT = b * S + BKT;
        kb[0] = *(const uint4*)&kn[(size_t)(kbT + krow) * (NH * NOPE) + h * NOPE + kg * 8];
        kb[1] = *(const uint4*)&kn[(size_t)(kbT + krow) * (NH * NOPE) + h * NOPE + kg * 8 + 64];
        kb[2] = *(const uint4*)&kr[(size_t)(kbT + krow) * ROPE + kg * 8];
    }

    for (int kt = 0; kt < nkt; kt++) {
        {
            uint32_t* dst = &sm.Vh[vrp * VSTRH + vcg];
            uint4 o0, o1;
            o0.x = prmt(vlo.x, vhi.x, 0x5410); o0.y = prmt(vlo.x, vhi.x, 0x7632);
            o0.z = prmt(vlo.y, vhi.y, 0x5410); o0.w = prmt(vlo.y, vhi.y, 0x7632);
            o1.x = prmt(vlo.z, vhi.z, 0x5410); o1.y = prmt(vlo.z, vhi.z, 0x7632);
            o1.z = prmt(vlo.w, vhi.w, 0x5410); o1.w = prmt(vlo.w, vhi.w, 0x7632);
            *(uint4*)&dst[0] = o0;
            *(uint4*)&dst[4] = o1;
        }

        float c[4][4];
#pragma unroll
        for (int j = 0; j < 4; j++)
#pragma unroll
            for (int cc = 0; cc < 4; cc++) c[j][cc] = 0.f;

#pragma unroll
        for (int ks = 0; ks < 12; ks++) {
            const uint32_t* ap = &sm.Qf[(((mtile * 12 + ks) * 4) << 5) + lane];
            uint32_t a0 = ap[0], a1 = ap[32], a2 = ap[64], a3 = ap[96];
#pragma unroll
            for (int j = 0; j < 4; j++) {
                const uint32_t* bp = &sm.Kf[((((ntb + j) * 12 + ks) * 2) << 5) + lane];
                mma_f16(c[j][0], c[j][1], c[j][2], c[j][3],
                        a0, a1, a2, a3, bp[0], bp[32]);
            }
        }

        {
            const bool diag = (kt >= 2 * qt);
#pragma unroll
            for (int j = 0; j < 4; j++) {
                int col = (ntb + j) * 8 + rid * 2;
                int ki0 = kt * BKT + col;
                c[j][0] *= SM_SCALE2; c[j][1] *= SM_SCALE2;
                c[j][2] *= SM_SCALE2; c[j][3] *= SM_SCALE2;
                if (diag) {
                    int qi0 = qt * BQ + row0;
                    int qi1 = qi0 + 8;
                    if (ki0     > qi0) c[j][0] = MASK2;
                    if (ki0 + 1 > qi0) c[j][1] = MASK2;
                    if (ki0     > qi1) c[j][2] = MASK2;
                    if (ki0 + 1 > qi1) c[j][3] = MASK2;
                }
            }
        }

        {
            float mx0 = fmaxf(fmaxf(c[0][0], c[0][1]), fmaxf(c[1][0], c[1][1]));
            mx0 = fmaxf(mx0, fmaxf(fmaxf(c[2][0], c[2][1]), fmaxf(c[3][0], c[3][1])));
            float mx1 = fmaxf(fmaxf(c[0][2], c[0][3]), fmaxf(c[1][2], c[1][3]));
            mx1 = fmaxf(mx1, fmaxf(fmaxf(c[2][2], c[2][3]), fmaxf(c[3][2], c[3][3])));
            mx0 = fmaxf(mx0, __shfl_xor_sync(0xffffffffu, mx0, 1));
            mx0 = fmaxf(mx0, __shfl_xor_sync(0xffffffffu, mx0, 2));
            mx1 = fmaxf(mx1, __shfl_xor_sync(0xffffffffu, mx1, 1));
            mx1 = fmaxf(mx1, __shfl_xor_sync(0xffffffffu, mx1, 2));
            if (rid == 0) {
                sm.rowmax[half][row0]     = mx0;
                sm.rowmax[half][row0 + 8] = mx1;
            }
        }
        __syncthreads();

        float al0, al1;
        {
            float f0 = fmaxf(sm.rowmax[0][row0],     sm.rowmax[1][row0]);
            float f1 = fmaxf(sm.rowmax[0][row0 + 8], sm.rowmax[1][row0 + 8]);
            float mn0 = fmaxf(m0, f0);
            float mn1 = fmaxf(m1, f1);
            al0 = exp2f(m0 - mn0);
            al1 = exp2f(m1 - mn1);
            m0 = mn0; m1 = mn1;

            float ps0 = 0.f, ps1 = 0.f;
#pragma unroll
            for (int j = 0; j < 4; j++) {
                float e0 = exp2f(c[j][0] - mn0);
                float e1 = exp2f(c[j][1] - mn0);
                float e2 = exp2f(c[j][2] - mn1);
                float e3 = exp2f(c[j][3] - mn1);
                ps0 += e0 + e1;
                ps1 += e2 + e3;
                int pidx = (ntb + j) * 4 + rid;
                sm.Ph[row0 * PSTRH + pidx]       = h2_as_u32(__floats2half2_rn(e0, e1));
                sm.Ph[(row0 + 8) * PSTRH + pidx] = h2_as_u32(__floats2half2_rn(e2, e3));
            }
            ps0 += __shfl_xor_sync(0xffffffffu, ps0, 1);
            ps0 += __shfl_xor_sync(0xffffffffu, ps0, 2);
            ps1 += __shfl_xor_sync(0xffffffffu, ps1, 1);
            ps1 += __shfl_xor_sync(0xffffffffu, ps1, 2);
            if (rid == 0) {
                sm.rowsum[half][row0]     = ps0;
                sm.rowsum[half][row0 + 8] = ps1;
            }
        }

        if (kt + 1 < nkt) {
            const int vT = b * S + (kt + 1) * BKT;
            vlo = *(const uint4*)&v[(size_t)(vT + 2 * vrp)     * (NH * VD) + h * VD + vcg];
            vhi = *(const uint4*)&v[(size_t)(vT + 2 * vrp + 1) * (NH * VD) + h * VD + vcg];
            st_bfrag_h<12>(sm.Kf, krow, kg * 8, kb[0]);
            st_bfrag_h<12>(sm.Kf, krow, kg * 8 + 64, kb[1]);
            st_bfrag_h<12>(sm.Kf, krow, 128 + kg * 8, kb[2]);
            if (kt + 2 < nkt) {
                const int kT = b * S + (kt + 2) * BKT;
                kb[0] = *(const uint4*)&kn[(size_t)(kT + krow) * (NH * NOPE) + h * NOPE + kg * 8];
                kb[1] = *(const uint4*)&kn[(size_t)(kT + krow) * (NH * NOPE) + h * NOPE + kg * 8 + 64];
                kb[2] = *(const uint4*)&kr[(size_t)(kT + krow) * ROPE + kg * 8];
            }
        }
        __syncthreads();

        {
            l0 = l0 * al0 + (sm.rowsum[0][row0]     + sm.rowsum[1][row0]);
            l1 = l1 * al1 + (sm.rowsum[0][row0 + 8] + sm.rowsum[1][row0 + 8]);
#pragma unroll
            for (int j = 0; j < 8; j++) {
                acc[j][0] *= al0; acc[j][1] *= al0;
                acc[j][2] *= al1; acc[j][3] *= al1;
            }
#pragma unroll
            for (int ks = 0; ks < 4; ks++) {
                const uint32_t a0 = sm.Ph[row0 * PSTRH + ks * 8 + rid];
                const uint32_t a1 = sm.Ph[(row0 + 8) * PSTRH + ks * 8 + rid];
                const uint32_t a2 = sm.Ph[row0 * PSTRH + ks * 8 + rid + 4];
                const uint32_t a3 = sm.Ph[(row0 + 8) * PSTRH + ks * 8 + rid + 4];
#pragma unroll
                for (int j = 0; j < 8; j++) {
                    const uint32_t b0 = sm.Vh[(ks * 8 + rid)     * VSTRH + nbv + j * 8 + qid];
                    const uint32_t b1 = sm.Vh[(ks * 8 + rid + 4) * VSTRH + nbv + j * 8 + qid];
                    mma_f16(acc[j][0], acc[j][1], acc[j][2], acc[j][3],
                            a0, a1, a2, a3, b0, b1);
                }
            }
        }
        __syncthreads();
    }

    {
        const float il0 = 1.f / l0;
        const float il1 = 1.f / l1;
        const int tok0 = qb + row0;
        const int tok1 = tok0 + 8;
#pragma unroll
        for (int j = 0; j < 8; j++) {
            const int col = nbv + j * 8 + rid * 2;
            *(float2*)&out[(size_t)tok0 * (NH * VD) + h * VD + col] =
                make_float2(acc[j][0] * il0, acc[j][1] * il0);
            *(float2*)&out[(size_t)tok1 * (NH * VD) + h * VD + col] =
                make_float2(acc[j][2] * il1, acc[j][3] * il1);
        }
    }
}

// ---------------------------------------------------------------------------
// Launch (Q path and KV path forked onto concurrent streams inside capture)
// ---------------------------------------------------------------------------
static void launch_gemm_s(cudaStream_t s, const float* A, const float* B, float* C,
                          int M, int N, int K, int round_out = 0, __half* Ch = nullptr)
{
    dim3 grid((N + 127) / 128, (M + 127) / 128);
    f16_gemm_kernel<<<grid, 256, 0, s>>>(A, B, C, Ch, M, N, K, round_out);
}

extern "C" void kernel_launch(void* const* d_in, const int* in_sizes, int n_in,
                              void* d_out, int out_size)
{
    const float* x         = (const float*)d_in[0];
    const float* W_cq      = (const float*)d_in[1];
    const float* q_scale   = (const float*)d_in[2];
    const float* W_dq_nope = (const float*)d_in[3];
    const float* W_dq_rope = (const float*)d_in[4];
    const float* W_ckv     = (const float*)d_in[5];
    const float* kv_scale  = (const float*)d_in[6];
    const float* W_dk_nope = (const float*)d_in[7];
    const float* W_dv      = (const float*)d_in[8];
    const float* W_krope   = (const float*)d_in[9];
    const float* W_o       = (const float*)d_in[10];
    float* out = (float*)d_out;

    float *cq, *ckv, *qrf, *krf, *att, *ctab, *stab;
    __half *qnh, *knh, *qrh, *krh, *vvh;
    cudaGetSymbolAddress((void**)&cq,   g_cq);
    cudaGetSymbolAddress((void**)&ckv,  g_ckv);
    cudaGetSymbolAddress((void**)&qrf,  g_qrope_f);
    cudaGetSymbolAddress((void**)&krf,  g_krope_f);
    cudaGetSymbolAddress((void**)&att,  g_attn);
    cudaGetSymbolAddress((void**)&ctab, g_ctab);
    cudaGetSymbolAddress((void**)&stab, g_stab);
    cudaGetSymbolAddress((void**)&qnh,  g_qnope_h);
    cudaGetSymbolAddress((void**)&knh,  g_knope_h);
    cudaGetSymbolAddress((void**)&qrh,  g_qrope_h);
    cudaGetSymbolAddress((void**)&krh,  g_krope_h);
    cudaGetSymbolAddress((void**)&vvh,  g_v_h);

    // Fork/join machinery (host-only cost; harness times graph replays).
    cudaStream_t s0 = 0;
    cudaStream_t skv;
    cudaEvent_t ev_fork, ev_kv;
    cudaStreamCreateWithFlags(&skv, cudaStreamNonBlocking);
    cudaEventCreateWithFlags(&ev_fork, cudaEventDisableTiming);
    cudaEventCreateWithFlags(&ev_kv,  cudaEventDisableTiming);

    // RoPE tables (needed by both paths)
    rope_table_kernel<<<(S * 32 + 255) / 256, 256, 0, s0>>>(ctab, stab);

    // ---- fork: KV path on skv ----
    cudaEventRecord(ev_fork, s0);
    cudaStreamWaitEvent(skv, ev_fork, 0);

    // KV path (skv)
    launch_gemm_s(skv, x, W_krope, krf, T, ROPE, H);
    rope_k_kernel<<<(T * 32 + 255) / 256, 256, 0, skv>>>(krf, krh, ctab, stab);
    launch_gemm_s(skv, x, W_ckv, ckv, T, KVR, H);
    rmsnorm_kernel<<<T, 256, 0, skv>>>(ckv, kv_scale, KVR);
    launch_gemm_s(skv, ckv, W_dk_nope, nullptr, T, NH * NOPE, KVR, 0, knh); // fp16 out
    launch_gemm_s(skv, ckv, W_dv, nullptr, T, NH * VD, KVR, 0, vvh);        // fp16 out
    cudaEventRecord(ev_kv, skv);

    // Q path (s0)
    launch_gemm_s(s0, x, W_cq, cq, T, QR, H);
    rmsnorm_kernel<<<T, 256, 0, s0>>>(cq, q_scale, QR);
    launch_gemm_s(s0, cq, W_dq_nope, nullptr, T, NH * NOPE, QR, 0, qnh);    // fp16 out
    launch_gemm_s(s0, cq, W_dq_rope, qrf, T, NH * ROPE, QR);
    rope_q_kernel<<<(T * NH * 32 + 255) / 256, 256, 0, s0>>>(qrf, qrh, ctab, stab);

    // ---- join ----
    cudaStreamWaitEvent(s0, ev_kv, 0);

    // Attention
    cudaFuncSetAttribute((const void*)attn_kernel,
                         cudaFuncAttributeMaxDynamicSharedMemorySize,
                         (int)sizeof(AttnSmem));
    attn_kernel<<<dim3(S / BQ, NH, BB), 512, sizeof(AttnSmem), s0>>>(qnh, qrh, knh, krh, vvh, att);

    // Output projection
    launch_gemm_s(s0, att, W_o, out, T, H, NH * VD);
}